// round 8
// baseline (speedup 1.0000x reference)
#include <cuda_runtime.h>

// Grad3D: out = |dx| + |dy| + |dz| with central differences, zero-padded.
// x shape (4, 1, 192, 224, 192) fp32, contiguous.
// Register D-march (R6 structure): each thread owns one (h, w4) quad, marches
// DCHUNK planes. z-derivative & center in registers; smem (2 plane buffers)
// serves lf/rt/up/dn. This round: 32-bit offsets + incremental pointers +
// __launch_bounds__(480,4) to reach 4 blocks/SM.

#define Nn 4
#define Dd 192
#define Hh 224
#define Ww 192
#define HW (Hh * Ww)          // 43008
#define DHW (Dd * HW)         // 8257536

#define BH 8                  // H output rows per block
#define DCHUNK 16             // D planes per block
#define NROWS (BH + 2)        // incl. halo rows (10)
#define ROWSTRIDE 200         // floats/row (800B): [3]=zero(w=-1), [4..195]=data, [196]=zero(w=192)
#define QPERROW (Ww / 4)      // 48
#define THREADS (NROWS * QPERROW)  // 480

__global__ void __launch_bounds__(THREADS, 4)
grad3d_kernel(const float* __restrict__ x, float* __restrict__ out)
{
    __shared__ __align__(16) float sm[2][NROWS * ROWSTRIDE];

    const int tid  = threadIdx.x;
    const int r    = tid / QPERROW;       // 0..9 (r=0, r=9 are halo rows)
    const int q    = tid - r * QPERROW;   // 0..47
    const int h0   = blockIdx.x * BH;     // 0..216
    const int d0   = blockIdx.y * DCHUNK; // 0..176
    const int n    = blockIdx.z;
    const int gh   = h0 - 1 + r;
    const bool inH  = (gh >= 0) && (gh < Hh);
    const bool comp = (r >= 1) && (r <= BH);

    // Zero guard columns (w=-1 at [3], w=W at [196]) in both buffers.
    if (q < 4) {
        int b    = q >> 1;
        int side = q & 1;
        sm[b][r * ROWSTRIDE + (side ? (4 + Ww) : 3)] = 0.0f;
    }

    // 32-bit offsets: max element offset 33.5M << 2^31.
    // src starts at plane d0-1; dst at plane d0. Both advance by HW per plane.
    const float* __restrict__ src =
        x + (size_t)n * DHW + (inH ? gh : 0) * Ww + q * 4 + (d0 - 1) * HW;
    float* __restrict__ dst =
        out + (size_t)n * DHW + (comp ? gh : 0) * Ww + q * 4 + d0 * HW;

    const int soff = r * ROWSTRIDE + 4 + q * 4;
    // valid D range for src (src points at plane d0-1+k when advanced k planes)
    int dcur = d0 - 1;   // plane index currently addressed by src

    auto ldq = [&](int off_planes) -> float4 {   // load plane dcur+off via src
        int d = dcur + off_planes;
        if (inH && (unsigned)d < (unsigned)Dd)
            return *reinterpret_cast<const float4*>(src + off_planes * HW);
        return make_float4(0.f, 0.f, 0.f, 0.f);
    };

    // Invariant entering iter k: regs r_prev=x[d-1], r_cur=x[d], r_next=x[d+1];
    // sm[d&1] holds plane d, where d = d0+k.
    float4 r_prev = ldq(0);
    float4 r_cur  = ldq(1);
    float4 r_next = ldq(2);
    *reinterpret_cast<float4*>(&sm[d0 & 1][soff]) = r_cur;
    __syncthreads();

#pragma unroll 2
    for (int k = 0; k < DCHUNK; ++k) {
        const int d = d0 + k;
        // Prefetch plane d+2 (consumed next iteration after rotation).
        float4 tmp = (k + 2 <= DCHUNK) ? ldq(3) : make_float4(0.f, 0.f, 0.f, 0.f);

        // Publish plane d+1 for next iteration's neighbor reads.
        if (k + 1 < DCHUNK)
            *reinterpret_cast<float4*>(&sm[(d + 1) & 1][soff]) = r_next;

        if (comp) {
            const float* cb = &sm[d & 1][soff];
            float  lf = cb[-1];                                          // guard at q==0
            float  rt = cb[4];                                           // guard at q==47
            float4 up = *reinterpret_cast<const float4*>(cb - ROWSTRIDE);
            float4 dn = *reinterpret_cast<const float4*>(cb + ROWSTRIDE);

            float4 o;
            o.x = 0.5f * (fabsf(r_cur.y - lf)      + fabsf(dn.x - up.x) + fabsf(r_next.x - r_prev.x));
            o.y = 0.5f * (fabsf(r_cur.z - r_cur.x) + fabsf(dn.y - up.y) + fabsf(r_next.y - r_prev.y));
            o.z = 0.5f * (fabsf(r_cur.w - r_cur.y) + fabsf(dn.z - up.z) + fabsf(r_next.z - r_prev.z));
            o.w = 0.5f * (fabsf(rt     - r_cur.z)  + fabsf(dn.w - up.w) + fabsf(r_next.w - r_prev.w));

            *reinterpret_cast<float4*>(dst) = o;
        }

        __syncthreads();   // sm[(d+1)&1] published; reads of sm[d&1] complete
        r_prev = r_cur; r_cur = r_next; r_next = tmp;
        src  += HW;
        dst  += HW;
        dcur += 1;
    }
}

extern "C" void kernel_launch(void* const* d_in, const int* in_sizes, int n_in,
                              void* d_out, int out_size)
{
    const float* x = (const float*)d_in[0];
    float* out = (float*)d_out;
    dim3 grid(Hh / BH, Dd / DCHUNK, Nn);   // 28 x 12 x 4 = 1344 blocks
    grad3d_kernel<<<grid, THREADS>>>(x, out);
}

// round 9
// speedup vs baseline: 1.0816x; 1.0816x over previous
#include <cuda_runtime.h>

// Grad3D: out = |dx| + |dy| + |dz| with central differences, zero-padded.
// x shape (4, 1, 192, 224, 192) fp32, contiguous.
// Barrier-free flat kernel: each thread owns one (h, w4) float4 quad and
// marches DCHUNK planes along D. pp/cc/nn live in registers (prefetch dist 2);
// up/dn/lf/rt are direct global loads of plane d, which is L1-resident (it was
// prefetched by all threads two iterations earlier). No smem, no __syncthreads.

#define Nn 4
#define Dd 192
#define Hh 224
#define Ww 192
#define HW (Hh * Ww)          // 43008
#define DHW (Dd * HW)         // 8257536

#define BH 8                  // H rows per block
#define DCHUNK 16             // D planes per block
#define QPERROW (Ww / 4)      // 48

__global__ void __launch_bounds__(BH * QPERROW)
grad3d_kernel(const float* __restrict__ x, float* __restrict__ out)
{
    const int q   = threadIdx.x;            // 0..47
    const int ry  = threadIdx.y;            // 0..7
    const int gh  = blockIdx.x * BH + ry;   // 0..223 (all valid, no halo threads)
    const int d0  = blockIdx.y * DCHUNK;    // 0..176
    const int n   = blockIdx.z;

    const bool hasUp = (gh > 0);
    const bool hasDn = (gh < Hh - 1);
    const bool hasLf = (q > 0);
    const bool hasRt = (q < QPERROW - 1);

    const float* __restrict__ p =
        x + (size_t)n * DHW + gh * Ww + q * 4 + d0 * HW;   // points at plane d0
    float* __restrict__ dst =
        out + (size_t)n * DHW + gh * Ww + q * 4 + d0 * HW;

    const float4 Z = make_float4(0.f, 0.f, 0.f, 0.f);

    // Register planes: pp=x[d-1], cc=x[d], nn=x[d+1], tmp=x[d+2] (prefetch).
    float4 pp = (d0 > 0) ? *reinterpret_cast<const float4*>(p - HW) : Z;
    float4 cc = *reinterpret_cast<const float4*>(p);
    float4 nn = *reinterpret_cast<const float4*>(p + HW);   // d0+1 <= 177 < Dd always

#pragma unroll 2
    for (int k = 0; k < DCHUNK; ++k) {
        const int d = d0 + k;

        // Fresh prefetch of plane d+2 (consumed as nn two iterations later).
        float4 tmp = (d + 2 < Dd) ? *reinterpret_cast<const float4*>(p + 2 * HW) : Z;

        // Neighbor reads on plane d — L1 hits (plane d prefetched 2 iters ago).
        float4 up = hasUp ? *reinterpret_cast<const float4*>(p - Ww) : Z;
        float4 dn = hasDn ? *reinterpret_cast<const float4*>(p + Ww) : Z;
        float  lf = hasLf ? p[-1] : 0.0f;
        float  rt = hasRt ? p[4]  : 0.0f;

        float4 o;
        o.x = 0.5f * (fabsf(cc.y - lf)   + fabsf(dn.x - up.x) + fabsf(nn.x - pp.x));
        o.y = 0.5f * (fabsf(cc.z - cc.x) + fabsf(dn.y - up.y) + fabsf(nn.y - pp.y));
        o.z = 0.5f * (fabsf(cc.w - cc.y) + fabsf(dn.z - up.z) + fabsf(nn.z - pp.z));
        o.w = 0.5f * (fabsf(rt   - cc.z) + fabsf(dn.w - up.w) + fabsf(nn.w - pp.w));

        *reinterpret_cast<float4*>(dst) = o;

        pp = cc; cc = nn; nn = tmp;
        p   += HW;
        dst += HW;
    }
}

extern "C" void kernel_launch(void* const* d_in, const int* in_sizes, int n_in,
                              void* d_out, int out_size)
{
    const float* x = (const float*)d_in[0];
    float* out = (float*)d_out;
    dim3 block(QPERROW, BH);                // 48 x 8 = 384 threads
    dim3 grid(Hh / BH, Dd / DCHUNK, Nn);    // 28 x 12 x 4 = 1344 blocks
    grad3d_kernel<<<grid, block>>>(x, out);
}